// round 4
// baseline (speedup 1.0000x reference)
#include <cuda_runtime.h>
#include <math.h>

// Problem constants
#define HH 768
#define WW 768
#define NIMG 32
#define HWI (768 * 768)
#define HWLL (768LL * 768LL)

// Tile: 128 cols x 64 rows per block; block (32,8); thread = 4 cols x 8 rows
#define TW 128
#define TH 64
#define SW2 136          // TW + 8 (4-col halo both sides, float4 aligned)
#define SH2 68           // TH + 4
#define BLOCKS_X (WW / TW)   // 6
#define BLOCKS_Y (HH / TH)   // 12
#define BPI (BLOCKS_X * BLOCKS_Y)  // 72 blocks per image

#define SP_FLOATS (SH2 * SW2)        // 9248
#define SMEM_BYTES ((SP_FLOATS + TH * TW) * 4)  // 69760

#define MIN_WEIGHT 0.1f

__device__ float g_part[NIMG * BPI];   // fully rewritten every run
__device__ int   g_cnt[NIMG];          // monotonic epoch counters (never reset)

__device__ __forceinline__ float tanh_a(float x) {
    float r;
    asm("tanh.approx.f32 %0, %1;" : "=f"(r) : "f"(x));
    return r;
}
__device__ __forceinline__ float sigm(float x) {
    return fmaf(0.5f, tanh_a(0.5f * x), 0.5f);
}

#define HSQ(r, hs, hq)                                                         \
{                                                                              \
    const float4 A = *reinterpret_cast<const float4*>(&sp[(r) * SW2 + j4]);    \
    const float4 B = *reinterpret_cast<const float4*>(&sp[(r) * SW2 + j4 + 4]);\
    const float4 C = *reinterpret_cast<const float4*>(&sp[(r) * SW2 + j4 + 8]);\
    hs.x = A.z + A.w + B.x + B.y + B.z;                                        \
    hs.y = hs.x - A.z + B.w;                                                   \
    hs.z = hs.y - A.w + C.x;                                                   \
    hs.w = hs.z - B.x + C.y;                                                   \
    const float qAz = A.z * A.z, qAw = A.w * A.w;                              \
    const float qBx = B.x * B.x, qBy = B.y * B.y;                              \
    const float qBz = B.z * B.z, qBw = B.w * B.w;                              \
    const float qCx = C.x * C.x, qCy = C.y * C.y;                              \
    hq.x = qAz + qAw + qBx + qBy + qBz;                                        \
    hq.y = hq.x - qAz + qBw;                                                   \
    hq.z = hq.y - qAw + qCx;                                                   \
    hq.w = hq.z - qBx + qCy;                                                   \
}

__global__ __launch_bounds__(256, 3) void k_fused(
    const float* __restrict__ yd,
    const float* __restrict__ ygt,
    float* __restrict__ out)
{
    extern __shared__ float smem[];
    float* sp = smem;                 // [SH2][SW2] sigmoid tile
    float* wt = smem + SP_FLOATS;     // [TH][TW] unscaled w stash
    __shared__ float wsum[8];
    __shared__ float s_scale;

    const int img  = blockIdx.z;
    const int col0 = blockIdx.x * TW;
    const int row0 = blockIdx.y * TH;
    const float* __restrict__ yimg = yd  + (long long)img * HWLL;
    const float* __restrict__ gimg = ygt + (long long)img * HWLL;
    float* __restrict__ oimg = out + (long long)img * HWLL;

    const int tid = threadIdx.y * 32 + threadIdx.x;

    // ---- fill p = sigmoid(y) tile (halo: 2 rows, 4 cols; OOB -> 0) ----
    for (int t = tid; t < SH2 * 34; t += 256) {
        const int li = t / 34;
        const int v  = t - li * 34;
        const int gi = row0 + li - 2;
        const int gj = col0 + v * 4 - 4;
        float4 r = make_float4(0.f, 0.f, 0.f, 0.f);
        if ((unsigned)gi < (unsigned)HH && (unsigned)gj <= (unsigned)(WW - 4)) {
            float4 yv = *reinterpret_cast<const float4*>(yimg + gi * WW + gj);
            r.x = sigm(yv.x); r.y = sigm(yv.y); r.z = sigm(yv.z); r.w = sigm(yv.w);
        }
        *reinterpret_cast<float4*>(&sp[li * SW2 + v * 4]) = r;
    }
    __syncthreads();

    const int j4   = threadIdx.x * 4;
    const int gj0  = col0 + j4;
    const int r0   = threadIdx.y * 8;

    float fcx[4], rinvI[4];
    #pragma unroll
    for (int m = 0; m < 4; ++m) {
        const int gj = gj0 + m;
        fcx[m] = (float)(min(gj, 2) + min(WW - 1 - gj, 2) + 1);
        rinvI[m] = __fdividef(1.0f, fcx[m] * 5.0f - 1.0f);  // interior-row reciprocal
    }

    float4 S = make_float4(0.f, 0.f, 0.f, 0.f);
    float4 Q = make_float4(0.f, 0.f, 0.f, 0.f);
    #pragma unroll
    for (int k = 0; k < 4; ++k) {
        float4 hs, hq;
        HSQ(r0 + k, hs, hq);
        S.x += hs.x; S.y += hs.y; S.z += hs.z; S.w += hs.w;
        Q.x += hq.x; Q.y += hq.y; Q.z += hq.z; Q.w += hq.w;
    }

    float lsum = 0.0f;

    #pragma unroll
    for (int o = 0; o < 8; ++o) {
        const int gi = row0 + r0 + o;
        const float4 gv = *reinterpret_cast<const float4*>(gimg + gi * WW + gj0);

        {   // incoming window row
            float4 hs, hq;
            HSQ(r0 + o + 4, hs, hq);
            S.x += hs.x; S.y += hs.y; S.z += hs.z; S.w += hs.w;
            Q.x += hq.x; Q.y += hq.y; Q.z += hq.z; Q.w += hq.w;
        }

        const float4 P0 = *reinterpret_cast<const float4*>(&sp[(r0 + o + 2) * SW2 + j4 + 4]);

        const bool  inner = (gi >= 2) & (gi < HH - 2);
        const float fcy   = (float)(min(gi, 2) + min(HH - 1 - gi, 2) + 1);

        float4 w;
        #define DO_COMP(c, mi)                                                  \
        {                                                                       \
            const float fnv  = fcx[mi] * fcy;                                   \
            const float rinv = inner ? rinvI[mi]                                \
                                     : __fdividef(1.0f, fnv - 1.0f);            \
            const float p0  = P0.c;                                             \
            const float acc = fmaf(fmaf(fnv, p0, -2.0f * S.c), p0, Q.c);        \
            const float cons = 1.0f - acc * rinv;                               \
            const float qq  = 1.0f - p0;                                        \
            const float l2p = __log2f(fmaxf(p0, 1e-37f));                       \
            const float l2q = __log2f(fmaxf(qq, 1e-37f));                       \
            const float ent = fmaf(p0, l2p, fmaf(qq, l2q, 1.0f));               \
            float ww = fmaxf(cons * ent, gv.c);                                 \
            w.c = fmaf(1.0f - MIN_WEIGHT, ww, MIN_WEIGHT);                      \
        }
        DO_COMP(x, 0)
        DO_COMP(y, 1)
        DO_COMP(z, 2)
        DO_COMP(w, 3)
        #undef DO_COMP

        *reinterpret_cast<float4*>(&wt[(r0 + o) * TW + j4]) = w;   // smem stash
        lsum += (w.x + w.y) + (w.z + w.w);

        if (o < 7) {   // leaving window row
            float4 hs, hq;
            HSQ(r0 + o, hs, hq);
            S.x -= hs.x; S.y -= hs.y; S.z -= hs.z; S.w -= hs.w;
            Q.x -= hq.x; Q.y -= hq.y; Q.z -= hq.z; Q.w -= hq.w;
        }
    }

    // ---- block reduction -> partial, then cross-CTA wait for the image ----
    #pragma unroll
    for (int o = 16; o; o >>= 1) lsum += __shfl_down_sync(0xffffffffu, lsum, o);
    if ((tid & 31) == 0) wsum[tid >> 5] = lsum;
    __syncthreads();
    if (tid < 8) {
        float v = wsum[tid];
        #pragma unroll
        for (int o = 4; o; o >>= 1) v += __shfl_down_sync(0xffu, v, o);
        if (tid == 0) {
            g_part[img * BPI + blockIdx.y * BLOCKS_X + blockIdx.x] = v;
            __threadfence();
            const int t0 = atomicAdd(&g_cnt[img], 1);
            const int target = t0 - (t0 % BPI) + BPI;   // epoch end (monotonic)
            volatile int* c = &g_cnt[img];
            while (*c < target) __nanosleep(100);
            __threadfence();
        }
    }
    __syncthreads();

    // ---- reduce the 72 partials, compute scale ----
    if (tid < 32) {
        float v = 0.0f;
        #pragma unroll
        for (int t = 0; t < 3; ++t) {
            const int idx = tid + t * 32;
            if (idx < BPI) v += g_part[img * BPI + idx];
        }
        #pragma unroll
        for (int o = 16; o; o >>= 1) v += __shfl_down_sync(0xffffffffu, v, o);
        if (tid == 0) s_scale = __fdividef((float)HWI, v);
    }
    __syncthreads();
    const float s = s_scale;

    // ---- scaled store: the ONLY global write of out ----
    #pragma unroll
    for (int o = 0; o < 8; ++o) {
        const int gi = row0 + r0 + o;
        float4 w = *reinterpret_cast<const float4*>(&wt[(r0 + o) * TW + j4]);
        w.x *= s; w.y *= s; w.z *= s; w.w *= s;
        *reinterpret_cast<float4*>(oimg + gi * WW + gj0) = w;
    }
}

extern "C" void kernel_launch(void* const* d_in, const int* in_sizes, int n_in,
                              void* d_out, int out_size) {
    const float* yd  = (const float*)d_in[0];
    const float* ygt = (const float*)d_in[1];
    float* out = (float*)d_out;

    cudaFuncSetAttribute(k_fused, cudaFuncAttributeMaxDynamicSharedMemorySize,
                         SMEM_BYTES);

    dim3 b1(32, 8);
    dim3 g1(BLOCKS_X, BLOCKS_Y, NIMG);      // (6, 12, 32)
    k_fused<<<g1, b1, SMEM_BYTES>>>(yd, ygt, out);
}